// round 1
// baseline (speedup 1.0000x reference)
#include <cuda_runtime.h>
#include <cstdint>

typedef unsigned long long ull;

// ---------------------------------------------------------------------------
// Packed f32x2 helpers (Blackwell FFMA2 — only reachable via PTX)
// ---------------------------------------------------------------------------
__device__ __forceinline__ void fma2(ull& d, ull a, ull b) {
    asm("fma.rn.f32x2 %0, %1, %2, %3;" : "=l"(d) : "l"(a), "l"(b), "l"(d));
}
__device__ __forceinline__ ull pack2(float v) {
    ull r;
    unsigned u = __float_as_uint(v);
    asm("mov.b64 %0, {%1, %1};" : "=l"(r) : "r"(u));
    return r;
}
__device__ __forceinline__ void unpack2(ull p, float& lo, float& hi) {
    unsigned a, b;
    asm("mov.b64 {%0, %1}, %2;" : "=r"(a), "=r"(b) : "l"(p));
    lo = __uint_as_float(a);
    hi = __uint_as_float(b);
}

// ---------------------------------------------------------------------------
// Scratch (no allocations allowed -> __device__ globals)
// partial sums per stage: ntiles * B * 128  (stages 1..4 only)
//   stage tiles: 128, 32, 8, 2  -> 262144 + 65536 + 16384 + 4096 = 348160
// ---------------------------------------------------------------------------
__device__ float g_psum[348160];
__device__ float g_psq[348160];
__device__ float g_mean[4 * 2048];
__device__ float g_rstd[4 * 2048];

// ---------------------------------------------------------------------------
// GEMM:  Y[b] (128 x HW) = W[b] (128 x 128) * X[b] (128 x HW)
// Block: one batch b, BN output columns, all 128 output rows.
// Threads: 256.  Thread tile: TM rows x TN(=8) cols, accumulated as f32x2
// pairs over adjacent columns.
// Fused deterministic per-block stats (sum, sumsq per output row).
// ---------------------------------------------------------------------------
template <int BN, bool DO_STATS>
__global__ void __launch_bounds__(256, 2)
gemm_stage_kernel(const float* __restrict__ X, const float* __restrict__ W,
                  float* __restrict__ Y, int HW,
                  int partial_off, int ntiles)
{
    constexpr int BK  = 16;
    constexpr int TN  = 8;
    constexpr int TCG = BN / TN;        // col groups: 16 (BN=128) or 8 (BN=64)
    constexpr int TOG = 256 / TCG;      // row groups: 16 or 32
    constexpr int TM  = 128 / TOG;      // rows per thread: 8 or 4

    // smem: W chunk (transposed) + X chunk; reused for the stats reduction
    constexpr int SM_FLOATS = BK * 128 + BK * BN;
    __shared__ __align__(16) float smem[SM_FLOATS];
    float* Wt = smem;             // [BK][128]  Wt[k][o]
    float* Xs = smem + BK * 128;  // [BK][BN]   Xs[k][p]

    const int b    = blockIdx.y;
    const int tile = blockIdx.x;
    const int p0   = tile * BN;
    const int tid  = threadIdx.x;
    const int cg   = tid % TCG;
    const int og   = tid / TCG;
    const int orow = og * TM;
    const int pcol = cg * TN;

    const float* Xb = X + (size_t)b * 128 * HW;
    const float* Wb = W + (size_t)b * 128 * 128;

    ull acc[TM][TN / 2];
    #pragma unroll
    for (int m = 0; m < TM; ++m)
        #pragma unroll
        for (int n = 0; n < TN / 2; ++n) acc[m][n] = 0ull;

    for (int kk = 0; kk < 128; kk += BK) {
        // --- load W chunk transposed: Wt[k][o] = Wb[o*128 + kk + k]
        #pragma unroll
        for (int j = 0; j < (BK * 128 / 4) / 256; ++j) {
            int i = tid + j * 256;          // over 512 float4
            int o = i >> 2;
            int q = (i & 3) * 4;            // k offset within chunk
            float4 v = *(const float4*)(Wb + o * 128 + kk + q);
            Wt[(q + 0) * 128 + o] = v.x;
            Wt[(q + 1) * 128 + o] = v.y;
            Wt[(q + 2) * 128 + o] = v.z;
            Wt[(q + 3) * 128 + o] = v.w;
        }
        // --- load X chunk: Xs[k][p] = Xb[(kk+k)*HW + p0 + p]
        constexpr int XV = BK * BN / 4;
        #pragma unroll
        for (int j = 0; j < XV / 256; ++j) {
            int i = tid + j * 256;
            int k  = i / (BN / 4);
            int p4 = i % (BN / 4);
            *(float4*)(Xs + k * BN + p4 * 4) =
                *(const float4*)(Xb + (size_t)(kk + k) * HW + p0 + p4 * 4);
        }
        __syncthreads();

        #pragma unroll
        for (int k = 0; k < BK; ++k) {
            float a[TM];
            #pragma unroll
            for (int m4 = 0; m4 < TM; m4 += 4) {
                float4 v = *(const float4*)(Wt + k * 128 + orow + m4);
                a[m4 + 0] = v.x; a[m4 + 1] = v.y;
                a[m4 + 2] = v.z; a[m4 + 3] = v.w;
            }
            ull b2[TN / 2];
            const ull* xr = (const ull*)(Xs + k * BN + pcol);
            #pragma unroll
            for (int n = 0; n < TN / 2; ++n) b2[n] = xr[n];
            #pragma unroll
            for (int m = 0; m < TM; ++m) {
                ull a2 = pack2(a[m]);
                #pragma unroll
                for (int n = 0; n < TN / 2; ++n) fma2(acc[m][n], a2, b2[n]);
            }
        }
        __syncthreads();
    }

    // --- epilogue: write Y, accumulate local stats
    float* Yb = Y + (size_t)b * 128 * HW + p0;
    float lsum[TM], lsq[TM];
    #pragma unroll
    for (int m = 0; m < TM; ++m) {
        float f[TN];
        #pragma unroll
        for (int n = 0; n < TN / 2; ++n) unpack2(acc[m][n], f[2 * n], f[2 * n + 1]);
        float4 v0 = make_float4(f[0], f[1], f[2], f[3]);
        float4 v1 = make_float4(f[4], f[5], f[6], f[7]);
        float* yrow = Yb + (size_t)(orow + m) * HW + pcol;
        *(float4*)(yrow)     = v0;
        *(float4*)(yrow + 4) = v1;
        if (DO_STATS) {
            float s = 0.f, q = 0.f;
            #pragma unroll
            for (int n = 0; n < TN; ++n) { s += f[n]; q += f[n] * f[n]; }
            lsum[m] = s; lsq[m] = q;
        }
    }

    if (DO_STATS) {
        // deterministic block reduction over col-groups, reusing smem
        float* S = smem;               // [TCG][128]
        float* Q = smem + TCG * 128;   // [TCG][128]
        #pragma unroll
        for (int m = 0; m < TM; ++m) {
            S[cg * 128 + orow + m] = lsum[m];
            Q[cg * 128 + orow + m] = lsq[m];
        }
        __syncthreads();
        if (tid < 128) {
            float s = 0.f, q = 0.f;
            #pragma unroll 4
            for (int c = 0; c < TCG; ++c) {
                s += S[c * 128 + tid];
                q += Q[c * 128 + tid];
            }
            size_t idx = (size_t)partial_off + ((size_t)b * ntiles + tile) * 128 + tid;
            g_psum[idx] = s;
            g_psq[idx]  = q;
        }
    }
}

// ---------------------------------------------------------------------------
// finalize: per (b,o) mean & rstd  (2048 channels per stage)
// ---------------------------------------------------------------------------
__global__ void finalize_kernel(int partial_off, int ntiles, float invHW, int stats_off)
{
    int idx = blockIdx.x * blockDim.x + threadIdx.x;
    if (idx >= 2048) return;
    int b = idx >> 7, o = idx & 127;
    float s = 0.f, q = 0.f;
    for (int t = 0; t < ntiles; ++t) {
        size_t j = (size_t)partial_off + ((size_t)b * ntiles + t) * 128 + o;
        s += g_psum[j];
        q += g_psq[j];
    }
    float m = s * invHW;
    float v = fmaf(q, invHW, -m * m);
    g_mean[stats_off + idx] = m;
    g_rstd[stats_off + idx] = rsqrtf(v + 1e-5f);
}

// ---------------------------------------------------------------------------
// normalize: y = (y - mean) * rstd   (vectorized float4)
// ---------------------------------------------------------------------------
__global__ void norm_kernel(float* __restrict__ Y, int stats_off, int shift, int total4)
{
    int i = blockIdx.x * blockDim.x + threadIdx.x;
    if (i >= total4) return;
    int ch = i >> shift;                 // b*128 + o
    float m = g_mean[stats_off + ch];
    float r = g_rstd[stats_off + ch];
    float4 v = ((float4*)Y)[i];
    v.x = (v.x - m) * r;
    v.y = (v.y - m) * r;
    v.z = (v.z - m) * r;
    v.w = (v.w - m) * r;
    ((float4*)Y)[i] = v;
}

// ---------------------------------------------------------------------------
// launch
// ---------------------------------------------------------------------------
extern "C" void kernel_launch(void* const* d_in, const int* in_sizes, int n_in,
                              void* d_out, int out_size)
{
    // Identify inputs by element count (robust to interleaved or grouped order;
    // the five weight tensors share a size and appear in stage order).
    const float* xs[5] = {nullptr, nullptr, nullptr, nullptr, nullptr};
    const float* ws[5] = {nullptr, nullptr, nullptr, nullptr, nullptr};
    int wcount = 0;
    for (int i = 0; i < n_in; ++i) {
        const float* p = (const float*)d_in[i];
        switch (in_sizes[i]) {
            case 33554432: xs[0] = p; break;   // x1: 16*128*128*128
            case 8388608:  xs[1] = p; break;   // x2
            case 2097152:  xs[2] = p; break;   // x3
            case 524288:   xs[3] = p; break;   // x4
            case 131072:   xs[4] = p; break;   // x5
            case 262144:   if (wcount < 5) ws[wcount++] = p; break; // l{i}fs
            default: break;
        }
    }

    float* out = (float*)d_out;
    const int    HWs[5]    = {16384, 4096, 1024, 256, 64};
    const int    ntiles[5] = {128, 32, 8, 2, 1};
    const size_t yoff[5]   = {0, 33554432, 41943040, 44040192, 44564480};
    const int    poff[4]   = {0, 262144, 327680, 344064};

    // stages 1..4: BN=128, fused stats
    for (int s = 0; s < 4; ++s) {
        dim3 grid(ntiles[s], 16);
        gemm_stage_kernel<128, true><<<grid, 256>>>(
            xs[s], ws[s], out + yoff[s], HWs[s], poff[s], ntiles[s]);
    }
    // stage 5: BN=64, no norm
    {
        dim3 grid(1, 16);
        gemm_stage_kernel<64, false><<<grid, 256>>>(
            xs[4], ws[4], out + yoff[4], HWs[4], 0, 1);
    }

    // finalize stats
    for (int s = 0; s < 4; ++s) {
        finalize_kernel<<<8, 256>>>(poff[s], ntiles[s], 1.0f / HWs[s], s * 2048);
    }

    // normalize stages 1..4
    for (int s = 0; s < 4; ++s) {
        int total4 = 16 * 128 * HWs[s] / 4;
        int shift  = (s == 0) ? 12 : (s == 1) ? 10 : (s == 2) ? 8 : 6;
        int blocks = (total4 + 255) / 256;
        norm_kernel<<<blocks, 256>>>(out + yoff[s], s * 2048, shift, total4);
    }

    (void)out_size;
}